// round 10
// baseline (speedup 1.0000x reference)
#include <cuda_runtime.h>
#include <cuda_bf16.h>
#include <cstdint>

#define Bb 32
#define Nn 1024
#define Ff 3
#define Tt 32
#define Kk 3
#define Cc 64
#define Ct 64
#define FT (Ff*Tt)   // 96

// Scratch
__device__ float gY[(size_t)Bb * Kk * Nn * FT];            // 37.7 MB
__device__ __nv_bfloat16 gAh[(size_t)Kk * Nn * Nn];        // cheb^T hi [k][n][m]
__device__ __nv_bfloat16 gAl[(size_t)Kk * Nn * Nn];        // cheb^T lo
__device__ __nv_bfloat16 gXh[(size_t)Bb * FT * Nn];        // x^T hi [b][ft][m]
__device__ __nv_bfloat16 gXl[(size_t)Bb * FT * Nn];        // x^T lo
__device__ __align__(16) __nv_bfloat16 gWtH[3 * 64 * 72];  // W per-tap hi [tap][c][72]
__device__ __align__(16) __nv_bfloat16 gWtL[3 * 64 * 72];  // W per-tap lo

__device__ __forceinline__ uint32_t s2u(const void* p) {
    uint32_t a;
    asm("{ .reg .u64 t; cvta.to.shared.u64 t, %1; cvt.u32.u64 %0, t; }" : "=r"(a) : "l"(p));
    return a;
}
#define SWZ(o) ((o) ^ (((o) >> 3) & 0x70))

__device__ __forceinline__ void cp16(uint32_t dst, const void* src) {
    asm volatile("cp.async.cg.shared.global [%0], [%1], 16;" :: "r"(dst), "l"(src));
}
__device__ __forceinline__ void ldmx4(uint32_t* r, uint32_t addr) {
    asm volatile("ldmatrix.sync.aligned.m8n8.x4.shared.b16 {%0,%1,%2,%3}, [%4];"
                 : "=r"(r[0]), "=r"(r[1]), "=r"(r[2]), "=r"(r[3]) : "r"(addr));
}
__device__ __forceinline__ void mma16816(float* d, const uint32_t* a,
                                         uint32_t b0, uint32_t b1) {
    asm volatile(
        "mma.sync.aligned.m16n8k16.row.col.f32.bf16.bf16.f32 "
        "{%0,%1,%2,%3}, {%4,%5,%6,%7}, {%8,%9}, {%0,%1,%2,%3};"
        : "+f"(d[0]), "+f"(d[1]), "+f"(d[2]), "+f"(d[3])
        : "r"(a[0]), "r"(a[1]), "r"(a[2]), "r"(a[3]), "r"(b0), "r"(b1));
}

// ---------------------------------------------------------------------------
// Prep kernels
// ---------------------------------------------------------------------------
__global__ __launch_bounds__(256) void convert_cheb(const float* __restrict__ cheb)
{
    __shared__ float t[32][33];
    const int k = blockIdx.z, m0 = blockIdx.x * 32, n0 = blockIdx.y * 32;
    const int tx = threadIdx.x, ty = threadIdx.y;
    #pragma unroll
    for (int j = 0; j < 4; ++j)
        t[ty + j * 8][tx] = cheb[((size_t)(k * Nn + m0 + ty + j * 8)) * Nn + n0 + tx];
    __syncthreads();
    #pragma unroll
    for (int j = 0; j < 4; ++j) {
        const int n = n0 + ty + j * 8, m = m0 + tx;
        float v = t[tx][ty + j * 8];
        __nv_bfloat16 h = __float2bfloat16(v);
        __nv_bfloat16 l = __float2bfloat16(v - __bfloat162float(h));
        gAh[((size_t)(k * Nn + n)) * Nn + m] = h;
        gAl[((size_t)(k * Nn + n)) * Nn + m] = l;
    }
}

__global__ __launch_bounds__(256) void convert_x(const float* __restrict__ x)
{
    __shared__ float t[32][33];
    const int b = blockIdx.z, m0 = blockIdx.x * 32, f0 = blockIdx.y * 32;
    const int tx = threadIdx.x, ty = threadIdx.y;
    #pragma unroll
    for (int j = 0; j < 4; ++j)
        t[ty + j * 8][tx] = x[((size_t)(b * Nn + m0 + ty + j * 8)) * FT + f0 + tx];
    __syncthreads();
    #pragma unroll
    for (int j = 0; j < 4; ++j) {
        const int ft = f0 + ty + j * 8, m = m0 + tx;
        float v = t[tx][ty + j * 8];
        __nv_bfloat16 h = __float2bfloat16(v);
        __nv_bfloat16 l = __float2bfloat16(v - __bfloat162float(h));
        gXh[((size_t)b * FT + ft) * Nn + m] = h;
        gXl[((size_t)b * FT + ft) * Nn + m] = l;
    }
}

// W per-tap: gWt[tap][c][ci] (rows padded to 72 elems), ci pad zeroed
__global__ __launch_bounds__(256) void prep_wt(const float* __restrict__ w_time)
{
    int i = blockIdx.x * 256 + threadIdx.x;   // 3*64*72 = 13824
    if (i < 3 * 64 * 72) {
        int tap = i / (64 * 72), r = i - tap * (64 * 72);
        int c = r / 72, ci = r - c * 72;
        float v = (ci < 64) ? w_time[(c * 64 + ci) * 3 + tap] : 0.f;
        __nv_bfloat16 h = __float2bfloat16(v);
        __nv_bfloat16 l = __float2bfloat16(v - __bfloat162float(h));
        gWtH[i] = h;
        gWtL[i] = l;
    }
}

// ---------------------------------------------------------------------------
// mma.sync bf16-split GEMM (unchanged from round 6/7)
// ---------------------------------------------------------------------------
#define KC 64
#define ASZ (128 * KC * 2)
#define XSZ (96  * KC * 2)
#define SM_AH 0
#define SM_AL (SM_AH + ASZ)
#define SM_XH (SM_AL + ASZ)
#define SM_XL (SM_XH + XSZ)
#define GEMM_SMEM (SM_XL + XSZ)   // 57344

__global__ __launch_bounds__(256) void gemm_mma_kernel()
{
    extern __shared__ char smem[];
    const int n0 = blockIdx.x * 128;
    const int k  = blockIdx.y;
    const int b  = blockIdx.z;
    const int tid  = threadIdx.x;
    const int wid  = tid >> 5, lane = tid & 31;
    const int wm   = wid & 3;
    const int wn   = wid >> 2;
    const uint32_t smb = s2u(smem);

    const size_t aBase = ((size_t)k * Nn + n0) * Nn;
    const size_t xBase = (size_t)b * FT * Nn;

    float acc[2][6][4];
    #pragma unroll
    for (int i = 0; i < 2; ++i)
        #pragma unroll
        for (int j = 0; j < 6; ++j)
            #pragma unroll
            for (int q = 0; q < 4; ++q) acc[i][j][q] = 0.f;

    const int lrow = (lane & 7) + ((lane >> 3) & 1) * 8;
    const int lkb  = (lane >> 4) * 16;

    const int NCH = Nn / KC;   // 16
    for (int c = 0; c < NCH; ++c) {
        const size_t mOff = (size_t)c * KC;
        for (int i = tid; i < 1024; i += 256) {
            const int row = i >> 3, seg = i & 7;
            const uint32_t so = SWZ(row * 128 + seg * 16);
            const size_t gi = aBase + (size_t)row * Nn + mOff + seg * 8;
            cp16(smb + SM_AH + so, gAh + gi);
            cp16(smb + SM_AL + so, gAl + gi);
        }
        for (int i = tid; i < 768; i += 256) {
            const int row = i >> 3, seg = i & 7;
            const uint32_t so = SWZ(row * 128 + seg * 16);
            const size_t gi = xBase + (size_t)row * Nn + mOff + seg * 8;
            cp16(smb + SM_XH + so, gXh + gi);
            cp16(smb + SM_XL + so, gXl + gi);
        }
        asm volatile("cp.async.commit_group;" ::: "memory");
        asm volatile("cp.async.wait_group 0;" ::: "memory");
        __syncthreads();

        #pragma unroll
        for (int ks = 0; ks < 4; ++ks) {
            const int kb = ks * 32 + lkb;
            uint32_t ah[2][4], al[2][4];
            #pragma unroll
            for (int mf = 0; mf < 2; ++mf) {
                const int r = wm * 32 + mf * 16 + lrow;
                const uint32_t off = SWZ(r * 128 + kb);
                ldmx4(ah[mf], smb + SM_AH + off);
                ldmx4(al[mf], smb + SM_AL + off);
            }
            uint32_t xh[3][4], xl[3][4];
            #pragma unroll
            for (int blk = 0; blk < 3; ++blk) {
                const int r = wn * 48 + blk * 16 + lrow;
                const uint32_t off = SWZ(r * 128 + kb);
                ldmx4(xh[blk], smb + SM_XH + off);
                ldmx4(xl[blk], smb + SM_XL + off);
            }
            #pragma unroll
            for (int mf = 0; mf < 2; ++mf)
                #pragma unroll
                for (int blk = 0; blk < 3; ++blk)
                    #pragma unroll
                    for (int sub = 0; sub < 2; ++sub) {
                        float* d = acc[mf][blk * 2 + sub];
                        mma16816(d, ah[mf], xh[blk][sub], xh[blk][sub + 2]);
                        mma16816(d, ah[mf], xl[blk][sub], xl[blk][sub + 2]);
                        mma16816(d, al[mf], xh[blk][sub], xh[blk][sub + 2]);
                    }
        }
        __syncthreads();
    }

    const int qrow = lane >> 2;
    const int qcol = (lane & 3) * 2;
    #pragma unroll
    for (int mf = 0; mf < 2; ++mf) {
        #pragma unroll
        for (int nf = 0; nf < 6; ++nf) {
            const int nrow = n0 + wm * 32 + mf * 16 + qrow;
            const int col  = wn * 48 + nf * 8 + qcol;
            float* base = gY + ((size_t)((b * Kk + k) * Nn) + nrow) * FT + col;
            *(float2*)(base)          = make_float2(acc[mf][nf][0], acc[mf][nf][1]);
            *(float2*)(base + 8 * FT) = make_float2(acc[mf][nf][2], acc[mf][nf][3]);
        }
    }
}

// ---------------------------------------------------------------------------
// Fused epilogue, tap-shifted conv GEMM (no im2col scatter).
// S stored once: [nh][34 rows (t+1 padded)][ci], 144 B row stride.
// conv: 3 taps x 4 ks, B row base shifted by tap. po fp32 overlays S.
// ---------------------------------------------------------------------------
#define RW   144              // row stride bytes (72 bf16)
#define EW   0                // W taps hi [3][64] rows       27648
#define EWL  27648            //        lo                    27648
#define ES   55296            // S hi [2][34] rows             9792
#define ESL  65088            // S lo                          9792
#define EPO  55296            // fp32 [64][66] overlay on S   16896
#define EXS  74880            // 2*96 f32
#define EYK  75648            // 2*3*96 f32
#define ETH  77952            // 576 f32
#define EWR  80256            // [f][c] 192 f32
#define EBI  81024
#define EGM  81280
#define EBB  81536
#define EMU  81792            // 2*32 f32
#define ERS  82048            // 2*32 f32
#define ESMEM 82304
#define GRP 8

__global__ __launch_bounds__(256) void fused_epi_tc(
    const float* __restrict__ x,
    const float* __restrict__ theta,
    const float* __restrict__ w_res,
    const float* __restrict__ b_time, const float* __restrict__ b_res,
    const float* __restrict__ gamma,  const float* __restrict__ beta,
    float* __restrict__ out)
{
    extern __shared__ char smem[];
    float* smf = (float*)smem;
    const uint32_t smb = s2u(smem);
    const int ng0 = blockIdx.x * GRP;
    const int b   = blockIdx.y;
    const int tid = threadIdx.x;
    const int wid = tid >> 5, lane = tid & 31;
    const int wm  = wid & 3, wn = wid >> 2;
    const int lrow = (lane & 7) + ((lane >> 3) & 1) * 8;
    const int lkb  = (lane >> 4) * 16;
    const int qrow = lane >> 2, qcol = (lane & 3) * 2;

    // ---- persistent: W taps via cp.async, scalars ----
    for (int i = tid; i < 1728; i += 256) {
        cp16(smb + EW  + i * 16, (const char*)gWtH + i * 16);
        cp16(smb + EWL + i * 16, (const char*)gWtL + i * 16);
    }
    asm volatile("cp.async.commit_group;" ::: "memory");
    for (int i = tid; i < 576; i += 256) smf[ETH/4 + i] = theta[i];
    if (tid < 192) { int c = tid / 3, f = tid - c * 3; smf[EWR/4 + f * 64 + c] = w_res[tid]; }
    if (tid < 64) {
        smf[EBI/4 + tid] = b_time[tid] + b_res[tid];
        smf[EGM/4 + tid] = gamma[tid];
        smf[EBB/4 + tid] = beta[tid];
    }
    asm volatile("cp.async.wait_group 0;" ::: "memory");
    __syncthreads();

    const int nh   = tid >> 7;
    const int ltid = tid & 127;
    // theta stage: thread = (t, ci-group)
    const int tTh  = ltid >> 2;          // 0..31
    const int cig  = ltid & 3;           // 16 ci each
    // scalar stages
    const int c2i  = ltid >> 2;
    const int tB   = (ltid & 3) * 8;
    const int tS   = ltid >> 2;
    const int sS   = ltid & 3;

    for (int np = 0; np < GRP / 2; ++np) {
        const int n0 = ng0 + 2 * np;

        // ---- per-iter loads + zero boundary rows of S ----
        if (tid < 2 * FT) {
            int h = tid / FT, ft = tid - h * FT;
            smf[EXS/4 + h * FT + ft] = x[((size_t)(b * Nn + n0 + h)) * FT + ft];
        }
        for (int i = tid; i < 2 * Kk * FT; i += 256) {
            int h = i / (Kk * FT), r = i - h * (Kk * FT);
            int k = r / FT, ft = r - k * FT;
            smf[EYK/4 + i] = gY[((size_t)((b * Kk + k) * Nn + n0 + h)) * FT + ft];
        }
        {
            // 256 threads: region(hi/lo) x nh x {row0,row33} x 32 words
            // generic-pointer smem stores (NOT the cvta'd shared address!)
            const int region = tid >> 7;
            const int lz = tid & 127;
            const int znh = lz >> 6, zrr = (lz >> 5) & 1, seg = lz & 31;
            char* base = smem + (region ? ESL : ES);
            *(uint32_t*)(base + (znh * 34 + (zrr ? 33 : 0)) * RW + seg * 4) = 0u;
        }
        __syncthreads();

        // ---- theta + relu + hi/lo split -> S row (t+1), 16 ci contiguous ----
        {
            const int ci0 = cig * 16;
            float sacc[16];
            #pragma unroll
            for (int j = 0; j < 16; ++j) sacc[j] = 0.f;
            #pragma unroll
            for (int k = 0; k < Kk; ++k)
                #pragma unroll
                for (int f = 0; f < Ff; ++f) {
                    const float yv = smf[EYK/4 + nh * (Kk * FT) + k * FT + f * Tt + tTh];
                    const float* tp = &smf[ETH/4 + k * (Ff * Cc) + f * Cc + ci0];
                    #pragma unroll
                    for (int j = 0; j < 16; ++j) sacc[j] += yv * tp[j];
                }
            const uint32_t rowoff = (nh * 34 + tTh + 1) * RW + ci0 * 2;
            uint32_t hp[8], lp[8];
            #pragma unroll
            for (int jj = 0; jj < 8; ++jj) {
                const float v0 = fmaxf(sacc[2 * jj],     0.f);
                const float v1 = fmaxf(sacc[2 * jj + 1], 0.f);
                const __nv_bfloat16 h0 = __float2bfloat16(v0);
                const __nv_bfloat16 h1 = __float2bfloat16(v1);
                const __nv_bfloat16 l0 = __float2bfloat16(v0 - __bfloat162float(h0));
                const __nv_bfloat16 l1 = __float2bfloat16(v1 - __bfloat162float(h1));
                hp[jj] = (uint32_t)__bfloat16_as_ushort(h0)
                       | ((uint32_t)__bfloat16_as_ushort(h1) << 16);
                lp[jj] = (uint32_t)__bfloat16_as_ushort(l0)
                       | ((uint32_t)__bfloat16_as_ushort(l1) << 16);
            }
            uint32_t* dh = (uint32_t*)(smem + ES  + rowoff);
            uint32_t* dl = (uint32_t*)(smem + ESL + rowoff);
            #pragma unroll
            for (int jj = 0; jj < 8; ++jj) { dh[jj] = hp[jj]; dl[jj] = lp[jj]; }
        }
        __syncthreads();

        // ---- conv GEMM: 3 taps x 4 ks; warp tile 16c x 32cols (wn = nh) ----
        float acc[4][4];
        #pragma unroll
        for (int i = 0; i < 4; ++i)
            #pragma unroll
            for (int q = 0; q < 4; ++q) acc[i][q] = 0.f;

        #pragma unroll
        for (int tap = 0; tap < 3; ++tap) {
            #pragma unroll
            for (int ks = 0; ks < 4; ++ks) {
                const int kb = ks * 32 + lkb;
                uint32_t ah[4], al[4], bh[2][4], bl[2][4];
                const uint32_t aoff = (tap * 64 + wm * 16 + lrow) * RW + kb;
                ldmx4(ah, smb + EW  + aoff);
                ldmx4(al, smb + EWL + aoff);
                #pragma unroll
                for (int cb = 0; cb < 2; ++cb) {
                    const uint32_t boff = (wn * 34 + cb * 16 + lrow + tap) * RW + kb;
                    ldmx4(bh[cb], smb + ES  + boff);
                    ldmx4(bl[cb], smb + ESL + boff);
                }
                #pragma unroll
                for (int cb = 0; cb < 2; ++cb)
                    #pragma unroll
                    for (int sub = 0; sub < 2; ++sub) {
                        float* d = acc[cb * 2 + sub];
                        mma16816(d, ah, bh[cb][sub], bh[cb][sub + 2]);
                        mma16816(d, ah, bl[cb][sub], bl[cb][sub + 2]);
                        mma16816(d, al, bh[cb][sub], bh[cb][sub + 2]);
                    }
            }
        }
        __syncthreads();   // all S reads done -> safe to overlay po

        // ---- write conv result to po [c][66] ----
        {
            float* po = smf + EPO/4;
            #pragma unroll
            for (int nf = 0; nf < 4; ++nf) {
                const int col = wn * 32 + nf * 8 + qcol;
                *(float2*)&po[(wm * 16 + qrow) * 66 + col]     = make_float2(acc[nf][0], acc[nf][1]);
                *(float2*)&po[(wm * 16 + qrow + 8) * 66 + col] = make_float2(acc[nf][2], acc[nf][3]);
            }
        }
        __syncthreads();

        // ---- residual + bias + relu ----
        float vlo[8], vhi[8];
        {
            float* po = smf + EPO/4;
            const int clo = 2 * c2i, chi = clo + 1;
            const float wl0 = smf[EWR/4 + 0 * 64 + clo], wl1 = smf[EWR/4 + 1 * 64 + clo],
                        wl2 = smf[EWR/4 + 2 * 64 + clo];
            const float wh0 = smf[EWR/4 + 0 * 64 + chi], wh1 = smf[EWR/4 + 1 * 64 + chi],
                        wh2 = smf[EWR/4 + 2 * 64 + chi];
            const float blo = smf[EBI/4 + clo], bhi = smf[EBI/4 + chi];
            const float* xs = &smf[EXS/4 + nh * FT];
            #pragma unroll
            for (int j = 0; j < 8; ++j) {
                const int t = tB + j, col = nh * 32 + t;
                const float x0 = xs[t], x1 = xs[32 + t], x2 = xs[64 + t];
                vlo[j] = fmaxf(po[clo * 66 + col] + blo + wl0 * x0 + wl1 * x1 + wl2 * x2, 0.f);
                vhi[j] = fmaxf(po[chi * 66 + col] + bhi + wh0 * x0 + wh1 * x1 + wh2 * x2, 0.f);
                po[clo * 66 + col] = vlo[j];
                po[chi * 66 + col] = vhi[j];
            }
        }
        __syncthreads();

        // ---- LN stats ----
        {
            const float* po = smf + EPO/4;
            float sum = 0.f, sq = 0.f;
            #pragma unroll
            for (int q = 0; q < 16; ++q) {
                const float v = po[(sS * 16 + q) * 66 + nh * 32 + tS];
                sum += v; sq += v * v;
            }
            sum += __shfl_xor_sync(0xffffffffu, sum, 1);
            sq  += __shfl_xor_sync(0xffffffffu, sq,  1);
            sum += __shfl_xor_sync(0xffffffffu, sum, 2);
            sq  += __shfl_xor_sync(0xffffffffu, sq,  2);
            if (sS == 0) {
                const float m = sum * (1.f / Ct);
                const float var = sq * (1.f / Ct) - m * m;
                smf[EMU/4 + nh * 32 + tS] = m;
                smf[ERS/4 + nh * 32 + tS] = rsqrtf(var + 1e-5f);
            }
        }
        __syncthreads();

        // ---- normalize + store ----
        {
            const int clo = 2 * c2i, chi = clo + 1;
            const float glo = smf[EGM/4 + clo], bl = smf[EBB/4 + clo];
            const float ghi = smf[EGM/4 + chi], bh = smf[EBB/4 + chi];
            float olo[8], ohi[8];
            #pragma unroll
            for (int j = 0; j < 8; ++j) {
                const int t = tB + j;
                const float mu = smf[EMU/4 + nh * 32 + t];
                const float rs = smf[ERS/4 + nh * 32 + t];
                olo[j] = (vlo[j] - mu) * rs * glo + bl;
                ohi[j] = (vhi[j] - mu) * rs * ghi + bh;
            }
            float* obase = out + ((size_t)(b * Nn + n0 + nh)) * Ct * Tt;
            *(float4*)(obase + clo * Tt + tB)     = make_float4(olo[0], olo[1], olo[2], olo[3]);
            *(float4*)(obase + clo * Tt + tB + 4) = make_float4(olo[4], olo[5], olo[6], olo[7]);
            *(float4*)(obase + chi * Tt + tB)     = make_float4(ohi[0], ohi[1], ohi[2], ohi[3]);
            *(float4*)(obase + chi * Tt + tB + 4) = make_float4(ohi[4], ohi[5], ohi[6], ohi[7]);
        }
        __syncthreads();
    }
}

// ---------------------------------------------------------------------------
extern "C" void kernel_launch(void* const* d_in, const int* in_sizes, int n_in,
                              void* d_out, int out_size)
{
    const float* x      = (const float*)d_in[0];
    const float* cheb   = (const float*)d_in[1];
    const float* theta  = (const float*)d_in[2];
    const float* w_time = (const float*)d_in[3];
    const float* b_time = (const float*)d_in[4];
    const float* w_res  = (const float*)d_in[5];
    const float* b_res  = (const float*)d_in[6];
    const float* gamma  = (const float*)d_in[7];
    const float* beta   = (const float*)d_in[8];
    float* out = (float*)d_out;

    cudaFuncSetAttribute(gemm_mma_kernel,
                         cudaFuncAttributeMaxDynamicSharedMemorySize, GEMM_SMEM);
    cudaFuncSetAttribute(fused_epi_tc,
                         cudaFuncAttributeMaxDynamicSharedMemorySize, ESMEM);

    prep_wt<<<54, 256>>>(w_time);
    convert_cheb<<<dim3(32, 32, 3), dim3(32, 8)>>>(cheb);
    convert_x<<<dim3(32, 3, 32), dim3(32, 8)>>>(x);
    gemm_mma_kernel<<<dim3(8, 3, 32), 256, GEMM_SMEM>>>();
    fused_epi_tc<<<dim3(Nn / GRP, Bb), 256, ESMEM>>>(
        x, theta, w_res, b_time, b_res, gamma, beta, out);
}

// round 11
// speedup vs baseline: 1.3010x; 1.3010x over previous
#include <cuda_runtime.h>
#include <cuda_bf16.h>
#include <cstdint>

#define Bb 32
#define Nn 1024
#define Ff 3
#define Tt 32
#define Kk 3
#define Cc 64
#define Ct 64
#define FT (Ff*Tt)   // 96

// Scratch
__device__ float gY[(size_t)Bb * Kk * Nn * FT];            // 37.7 MB
__device__ __nv_bfloat16 gAh[(size_t)Kk * Nn * Nn];        // cheb^T hi [k][n][m]
__device__ __nv_bfloat16 gAl[(size_t)Kk * Nn * Nn];        // cheb^T lo
__device__ __nv_bfloat16 gXh[(size_t)Bb * FT * Nn];        // x^T hi [b][ft][m]
__device__ __nv_bfloat16 gXl[(size_t)Bb * FT * Nn];        // x^T lo
__device__ __align__(16) __nv_bfloat16 gWtH[3 * 64 * 72];  // W per-tap hi [tap][c][72]
__device__ __align__(16) __nv_bfloat16 gWtL[3 * 64 * 72];  // W per-tap lo

__device__ __forceinline__ uint32_t s2u(const void* p) {
    uint32_t a;
    asm("{ .reg .u64 t; cvta.to.shared.u64 t, %1; cvt.u32.u64 %0, t; }" : "=r"(a) : "l"(p));
    return a;
}
#define SWZ(o) ((o) ^ (((o) >> 3) & 0x70))

__device__ __forceinline__ void cp16(uint32_t dst, const void* src) {
    asm volatile("cp.async.cg.shared.global [%0], [%1], 16;" :: "r"(dst), "l"(src));
}
__device__ __forceinline__ void ldmx4(uint32_t* r, uint32_t addr) {
    asm volatile("ldmatrix.sync.aligned.m8n8.x4.shared.b16 {%0,%1,%2,%3}, [%4];"
                 : "=r"(r[0]), "=r"(r[1]), "=r"(r[2]), "=r"(r[3]) : "r"(addr));
}
__device__ __forceinline__ void mma16816(float* d, const uint32_t* a,
                                         uint32_t b0, uint32_t b1) {
    asm volatile(
        "mma.sync.aligned.m16n8k16.row.col.f32.bf16.bf16.f32 "
        "{%0,%1,%2,%3}, {%4,%5,%6,%7}, {%8,%9}, {%0,%1,%2,%3};"
        : "+f"(d[0]), "+f"(d[1]), "+f"(d[2]), "+f"(d[3])
        : "r"(a[0]), "r"(a[1]), "r"(a[2]), "r"(a[3]), "r"(b0), "r"(b1));
}

// ---------------------------------------------------------------------------
// Prep kernels (unchanged)
// ---------------------------------------------------------------------------
__global__ __launch_bounds__(256) void convert_cheb(const float* __restrict__ cheb)
{
    __shared__ float t[32][33];
    const int k = blockIdx.z, m0 = blockIdx.x * 32, n0 = blockIdx.y * 32;
    const int tx = threadIdx.x, ty = threadIdx.y;
    #pragma unroll
    for (int j = 0; j < 4; ++j)
        t[ty + j * 8][tx] = cheb[((size_t)(k * Nn + m0 + ty + j * 8)) * Nn + n0 + tx];
    __syncthreads();
    #pragma unroll
    for (int j = 0; j < 4; ++j) {
        const int n = n0 + ty + j * 8, m = m0 + tx;
        float v = t[tx][ty + j * 8];
        __nv_bfloat16 h = __float2bfloat16(v);
        __nv_bfloat16 l = __float2bfloat16(v - __bfloat162float(h));
        gAh[((size_t)(k * Nn + n)) * Nn + m] = h;
        gAl[((size_t)(k * Nn + n)) * Nn + m] = l;
    }
}

__global__ __launch_bounds__(256) void convert_x(const float* __restrict__ x)
{
    __shared__ float t[32][33];
    const int b = blockIdx.z, m0 = blockIdx.x * 32, f0 = blockIdx.y * 32;
    const int tx = threadIdx.x, ty = threadIdx.y;
    #pragma unroll
    for (int j = 0; j < 4; ++j)
        t[ty + j * 8][tx] = x[((size_t)(b * Nn + m0 + ty + j * 8)) * FT + f0 + tx];
    __syncthreads();
    #pragma unroll
    for (int j = 0; j < 4; ++j) {
        const int ft = f0 + ty + j * 8, m = m0 + tx;
        float v = t[tx][ty + j * 8];
        __nv_bfloat16 h = __float2bfloat16(v);
        __nv_bfloat16 l = __float2bfloat16(v - __bfloat162float(h));
        gXh[((size_t)b * FT + ft) * Nn + m] = h;
        gXl[((size_t)b * FT + ft) * Nn + m] = l;
    }
}

__global__ __launch_bounds__(256) void prep_wt(const float* __restrict__ w_time)
{
    int i = blockIdx.x * 256 + threadIdx.x;   // 3*64*72 = 13824
    if (i < 3 * 64 * 72) {
        int tap = i / (64 * 72), r = i - tap * (64 * 72);
        int c = r / 72, ci = r - c * 72;
        float v = (ci < 64) ? w_time[(c * 64 + ci) * 3 + tap] : 0.f;
        __nv_bfloat16 h = __float2bfloat16(v);
        __nv_bfloat16 l = __float2bfloat16(v - __bfloat162float(h));
        gWtH[i] = h;
        gWtL[i] = l;
    }
}

// ---------------------------------------------------------------------------
// mma.sync bf16-split GEMM (unchanged)
// ---------------------------------------------------------------------------
#define KC 64
#define ASZ (128 * KC * 2)
#define XSZ (96  * KC * 2)
#define SM_AH 0
#define SM_AL (SM_AH + ASZ)
#define SM_XH (SM_AL + ASZ)
#define SM_XL (SM_XH + XSZ)
#define GEMM_SMEM (SM_XL + XSZ)   // 57344

__global__ __launch_bounds__(256) void gemm_mma_kernel()
{
    extern __shared__ char smem[];
    const int n0 = blockIdx.x * 128;
    const int k  = blockIdx.y;
    const int b  = blockIdx.z;
    const int tid  = threadIdx.x;
    const int wid  = tid >> 5, lane = tid & 31;
    const int wm   = wid & 3;
    const int wn   = wid >> 2;
    const uint32_t smb = s2u(smem);

    const size_t aBase = ((size_t)k * Nn + n0) * Nn;
    const size_t xBase = (size_t)b * FT * Nn;

    float acc[2][6][4];
    #pragma unroll
    for (int i = 0; i < 2; ++i)
        #pragma unroll
        for (int j = 0; j < 6; ++j)
            #pragma unroll
            for (int q = 0; q < 4; ++q) acc[i][j][q] = 0.f;

    const int lrow = (lane & 7) + ((lane >> 3) & 1) * 8;
    const int lkb  = (lane >> 4) * 16;

    const int NCH = Nn / KC;   // 16
    for (int c = 0; c < NCH; ++c) {
        const size_t mOff = (size_t)c * KC;
        for (int i = tid; i < 1024; i += 256) {
            const int row = i >> 3, seg = i & 7;
            const uint32_t so = SWZ(row * 128 + seg * 16);
            const size_t gi = aBase + (size_t)row * Nn + mOff + seg * 8;
            cp16(smb + SM_AH + so, gAh + gi);
            cp16(smb + SM_AL + so, gAl + gi);
        }
        for (int i = tid; i < 768; i += 256) {
            const int row = i >> 3, seg = i & 7;
            const uint32_t so = SWZ(row * 128 + seg * 16);
            const size_t gi = xBase + (size_t)row * Nn + mOff + seg * 8;
            cp16(smb + SM_XH + so, gXh + gi);
            cp16(smb + SM_XL + so, gXl + gi);
        }
        asm volatile("cp.async.commit_group;" ::: "memory");
        asm volatile("cp.async.wait_group 0;" ::: "memory");
        __syncthreads();

        #pragma unroll
        for (int ks = 0; ks < 4; ++ks) {
            const int kb = ks * 32 + lkb;
            uint32_t ah[2][4], al[2][4];
            #pragma unroll
            for (int mf = 0; mf < 2; ++mf) {
                const int r = wm * 32 + mf * 16 + lrow;
                const uint32_t off = SWZ(r * 128 + kb);
                ldmx4(ah[mf], smb + SM_AH + off);
                ldmx4(al[mf], smb + SM_AL + off);
            }
            uint32_t xh[3][4], xl[3][4];
            #pragma unroll
            for (int blk = 0; blk < 3; ++blk) {
                const int r = wn * 48 + blk * 16 + lrow;
                const uint32_t off = SWZ(r * 128 + kb);
                ldmx4(xh[blk], smb + SM_XH + off);
                ldmx4(xl[blk], smb + SM_XL + off);
            }
            #pragma unroll
            for (int mf = 0; mf < 2; ++mf)
                #pragma unroll
                for (int blk = 0; blk < 3; ++blk)
                    #pragma unroll
                    for (int sub = 0; sub < 2; ++sub) {
                        float* d = acc[mf][blk * 2 + sub];
                        mma16816(d, ah[mf], xh[blk][sub], xh[blk][sub + 2]);
                        mma16816(d, ah[mf], xl[blk][sub], xl[blk][sub + 2]);
                        mma16816(d, al[mf], xh[blk][sub], xh[blk][sub + 2]);
                    }
        }
        __syncthreads();
    }

    const int qrow = lane >> 2;
    const int qcol = (lane & 3) * 2;
    #pragma unroll
    for (int mf = 0; mf < 2; ++mf) {
        #pragma unroll
        for (int nf = 0; nf < 6; ++nf) {
            const int nrow = n0 + wm * 32 + mf * 16 + qrow;
            const int col  = wn * 48 + nf * 8 + qcol;
            float* base = gY + ((size_t)((b * Kk + k) * Nn) + nrow) * FT + col;
            *(float2*)(base)          = make_float2(acc[mf][nf][0], acc[mf][nf][1]);
            *(float2*)(base + 8 * FT) = make_float2(acc[mf][nf][2], acc[mf][nf][3]);
        }
    }
}

// ---------------------------------------------------------------------------
// Fused epilogue: 4 n per iteration, tap-shifted conv GEMM, cp.async prefetch.
// S: [nq 0..3][34 rows][72 bf16] hi+lo; conv warp tile 32c x 32cols (wn = nq).
// po fp32 [64][130] overlays S. YK/XS double-buffered via cp.async.
// ---------------------------------------------------------------------------
#define RW    144
#define EW    0                 // W hi  27648
#define EWL   27648             // W lo  27648
#define ES    55296             // S hi  4*34*144 = 19584
#define ESL   74880             // S lo  19584            -> 94464
#define EPO   55296             // fp32 [64][130] overlay (33280)
#define EXS   94464             // [2][4][96] f32 = 3072
#define EYK   97536             // [2][4][3][96] f32 = 9216
#define ETH   106752            // 2304
#define EWR   109056            // 768
#define EBI   109824            // 256
#define EGM   110080
#define EBB   110336
#define EMU   110592            // 128 f32
#define ERS   111104            // 128 f32
#define ESMEM 111616
#define GRP   8
#define POW   130

__global__ __launch_bounds__(256) void fused_epi_tc(
    const float* __restrict__ x,
    const float* __restrict__ theta,
    const float* __restrict__ w_res,
    const float* __restrict__ b_time, const float* __restrict__ b_res,
    const float* __restrict__ gamma,  const float* __restrict__ beta,
    float* __restrict__ out)
{
    extern __shared__ char smem[];
    float* smf = (float*)smem;
    const uint32_t smb = s2u(smem);
    const int ng0 = blockIdx.x * GRP;
    const int b   = blockIdx.y;
    const int tid = threadIdx.x;
    const int wid = tid >> 5, lane = tid & 31;
    const int wm  = wid & 1, wn = wid >> 1;          // conv: 2 c-warps x 4 col-warps
    const int lrow = (lane & 7) + ((lane >> 3) & 1) * 8;
    const int lkb  = (lane >> 4) * 16;
    const int qrow = lane >> 2, qcol = (lane & 3) * 2;

    // ---- persistent: W taps via cp.async, scalars ----
    for (int i = tid; i < 1728; i += 256) {
        cp16(smb + EW  + i * 16, (const char*)gWtH + i * 16);
        cp16(smb + EWL + i * 16, (const char*)gWtL + i * 16);
    }
    asm volatile("cp.async.commit_group;" ::: "memory");
    for (int i = tid; i < 576; i += 256) smf[ETH/4 + i] = theta[i];
    if (tid < 192) { int c = tid / 3, f = tid - c * 3; smf[EWR/4 + f * 64 + c] = w_res[tid]; }
    if (tid < 64) {
        smf[EBI/4 + tid] = b_time[tid] + b_res[tid];
        smf[EGM/4 + tid] = gamma[tid];
        smf[EBB/4 + tid] = beta[tid];
    }
    asm volatile("cp.async.wait_group 0;" ::: "memory");
    __syncthreads();

    // prefetch helper: YK (288 cp16) + XS (96 cp16) for 4 n starting at ng0+4*npx
    auto issue_prefetch = [&](int npx, int buf) {
        const int n0x = ng0 + 4 * npx;
        for (int i = tid; i < 384; i += 256) {
            if (i < 288) {
                const int h = i / 72, r = i - h * 72;
                const int k = r / 24, seg = r - k * 24;
                const uint32_t dst = smb + EYK + buf * 4608 + ((h * 3 + k) * 96 + seg * 4) * 4;
                cp16(dst, gY + ((size_t)((b * Kk + k) * Nn + n0x + h)) * FT + seg * 4);
            } else {
                const int j = i - 288;
                const int h = j / 24, seg = j - h * 24;
                const uint32_t dst = smb + EXS + buf * 1536 + (h * 96 + seg * 4) * 4;
                cp16(dst, x + ((size_t)(b * Nn + n0x + h)) * FT + seg * 4);
            }
        }
        asm volatile("cp.async.commit_group;" ::: "memory");
    };

    // thread mappings
    const int nqT  = tid >> 6;           // theta / residual: which n of 4
    const int lT   = tid & 63;
    const int tTh  = lT & 31;            // theta: t
    const int cig  = lT >> 5;            // theta: ci half (32 each)
    const int cpr  = lT >> 1;            // residual: c pair 0..31
    const int tHv  = (lT & 1) * 16;      // residual: t half (16)
    const int colS = tid >> 1;           // LN: column 0..127
    const int sS   = tid & 1;

    issue_prefetch(0, 0);

    #pragma unroll 1
    for (int np = 0; np < 2; ++np) {
        const int buf = np;
        const int n0 = ng0 + 4 * np;

        if (np == 0) {
            issue_prefetch(1, 1);
            asm volatile("cp.async.wait_group 1;" ::: "memory");
        } else {
            asm volatile("cp.async.wait_group 0;" ::: "memory");
        }

        // zero boundary rows of S (rows nq*34+0 and nq*34+33, hi+lo): 576 words
        for (int i = tid; i < 576; i += 256) {
            const int region = i / 288, r = i - region * 288;
            const int nq = r / 72, rr = (r / 36) % 2, seg = r % 36;
            char* base = smem + (region ? ESL : ES);
            *(uint32_t*)(base + (nq * 34 + (rr ? 33 : 0)) * RW + seg * 4) = 0u;
        }
        __syncthreads();

        // ---- theta + relu + hi/lo split -> S row (t+1), 32 ci per thread ----
        {
            const int ci0 = cig * 32;
            float sacc[32];
            #pragma unroll
            for (int j = 0; j < 32; ++j) sacc[j] = 0.f;
            #pragma unroll
            for (int k = 0; k < Kk; ++k)
                #pragma unroll
                for (int f = 0; f < Ff; ++f) {
                    const float yv = smf[EYK/4 + buf * 1152 + (nqT * 3 + k) * 96 + f * Tt + tTh];
                    const float* tp = &smf[ETH/4 + k * (Ff * Cc) + f * Cc + ci0];
                    #pragma unroll
                    for (int j = 0; j < 32; ++j) sacc[j] += yv * tp[j];
                }
            const uint32_t rowoff = (nqT * 34 + tTh + 1) * RW + ci0 * 2;
            uint32_t* dh = (uint32_t*)(smem + ES  + rowoff);
            uint32_t* dl = (uint32_t*)(smem + ESL + rowoff);
            #pragma unroll
            for (int jj = 0; jj < 16; ++jj) {
                const float v0 = fmaxf(sacc[2 * jj],     0.f);
                const float v1 = fmaxf(sacc[2 * jj + 1], 0.f);
                const __nv_bfloat16 h0 = __float2bfloat16(v0);
                const __nv_bfloat16 h1 = __float2bfloat16(v1);
                const __nv_bfloat16 l0 = __float2bfloat16(v0 - __bfloat162float(h0));
                const __nv_bfloat16 l1 = __float2bfloat16(v1 - __bfloat162float(h1));
                dh[jj] = (uint32_t)__bfloat16_as_ushort(h0)
                       | ((uint32_t)__bfloat16_as_ushort(h1) << 16);
                dl[jj] = (uint32_t)__bfloat16_as_ushort(l0)
                       | ((uint32_t)__bfloat16_as_ushort(l1) << 16);
            }
        }
        __syncthreads();

        // ---- conv GEMM: warp tile 32c x 32cols (sub-slice nq = wn) ----
        float acc[2][4][4];
        #pragma unroll
        for (int i = 0; i < 2; ++i)
            #pragma unroll
            for (int j = 0; j < 4; ++j)
                #pragma unroll
                for (int q = 0; q < 4; ++q) acc[i][j][q] = 0.f;

        #pragma unroll
        for (int tap = 0; tap < 3; ++tap) {
            #pragma unroll
            for (int ks = 0; ks < 4; ++ks) {
                const int kb = ks * 32 + lkb;
                uint32_t ah[2][4], al[2][4], bh[2][4], bl[2][4];
                #pragma unroll
                for (int mf = 0; mf < 2; ++mf) {
                    const uint32_t aoff = (tap * 64 + wm * 32 + mf * 16 + lrow) * RW + kb;
                    ldmx4(ah[mf], smb + EW  + aoff);
                    ldmx4(al[mf], smb + EWL + aoff);
                }
                #pragma unroll
                for (int cb = 0; cb < 2; ++cb) {
                    const uint32_t boff = (wn * 34 + cb * 16 + lrow + tap) * RW + kb;
                    ldmx4(bh[cb], smb + ES  + boff);
                    ldmx4(bl[cb], smb + ESL + boff);
                }
                #pragma unroll
                for (int mf = 0; mf < 2; ++mf)
                    #pragma unroll
                    for (int cb = 0; cb < 2; ++cb)
                        #pragma unroll
                        for (int sub = 0; sub < 2; ++sub) {
                            float* d = acc[mf][cb * 2 + sub];
                            mma16816(d, ah[mf], bh[cb][sub], bh[cb][sub + 2]);
                            mma16816(d, ah[mf], bl[cb][sub], bl[cb][sub + 2]);
                            mma16816(d, al[mf], bh[cb][sub], bh[cb][sub + 2]);
                        }
            }
        }
        __syncthreads();   // all S reads done -> safe to overlay po

        // ---- write conv result to po [c][130] (col = wn*32 + t) ----
        {
            float* po = smf + EPO/4;
            #pragma unroll
            for (int mf = 0; mf < 2; ++mf)
                #pragma unroll
                for (int nf = 0; nf < 4; ++nf) {
                    const int c = wm * 32 + mf * 16 + qrow;
                    const int col = wn * 32 + nf * 8 + qcol;
                    *(float2*)&po[c * POW + col]       = make_float2(acc[mf][nf][0], acc[mf][nf][1]);
                    *(float2*)&po[(c + 8) * POW + col] = make_float2(acc[mf][nf][2], acc[mf][nf][3]);
                }
        }
        __syncthreads();

        // ---- residual + bias + relu (per thread: c pair x 16 t of sub-slice nqT) ----
        float vlo[16], vhi[16];
        {
            float* po = smf + EPO/4;
            const int clo = 2 * cpr, chi = clo + 1;
            const float wl0 = smf[EWR/4 + 0 * 64 + clo], wl1 = smf[EWR/4 + 1 * 64 + clo],
                        wl2 = smf[EWR/4 + 2 * 64 + clo];
            const float wh0 = smf[EWR/4 + 0 * 64 + chi], wh1 = smf[EWR/4 + 1 * 64 + chi],
                        wh2 = smf[EWR/4 + 2 * 64 + chi];
            const float blo = smf[EBI/4 + clo], bhi = smf[EBI/4 + chi];
            const float* xs = &smf[EXS/4 + buf * 384 + nqT * 96];
            #pragma unroll
            for (int j = 0; j < 16; ++j) {
                const int t = tHv + j, col = nqT * 32 + t;
                const float x0 = xs[t], x1 = xs[32 + t], x2 = xs[64 + t];
                vlo[j] = fmaxf(po[clo * POW + col] + blo + wl0 * x0 + wl1 * x1 + wl2 * x2, 0.f);
                vhi[j] = fmaxf(po[chi * POW + col] + bhi + wh0 * x0 + wh1 * x1 + wh2 * x2, 0.f);
                po[clo * POW + col] = vlo[j];
                po[chi * POW + col] = vhi[j];
            }
        }
        __syncthreads();

        // ---- LN stats over channel (128 cols, 2 threads/col) ----
        {
            const float* po = smf + EPO/4;
            float sum = 0.f, sq = 0.f;
            #pragma unroll
            for (int q = 0; q < 32; ++q) {
                const float v = po[(sS * 32 + q) * POW + colS];
                sum += v; sq += v * v;
            }
            sum += __shfl_xor_sync(0xffffffffu, sum, 1);
            sq  += __shfl_xor_sync(0xffffffffu, sq,  1);
            if (sS == 0) {
                const float m = sum * (1.f / Ct);
                const float var = sq * (1.f / Ct) - m * m;
                smf[EMU/4 + colS] = m;
                smf[ERS/4 + colS] = rsqrtf(var + 1e-5f);
            }
        }
        __syncthreads();

        // ---- normalize from regs + store ----
        {
            const int clo = 2 * cpr, chi = clo + 1;
            const float glo = smf[EGM/4 + clo], bl = smf[EBB/4 + clo];
            const float ghi = smf[EGM/4 + chi], bh = smf[EBB/4 + chi];
            float olo[16], ohi[16];
            #pragma unroll
            for (int j = 0; j < 16; ++j) {
                const int col = nqT * 32 + tHv + j;
                const float mu = smf[EMU/4 + col];
                const float rs = smf[ERS/4 + col];
                olo[j] = (vlo[j] - mu) * rs * glo + bl;
                ohi[j] = (vhi[j] - mu) * rs * ghi + bh;
            }
            float* obase = out + ((size_t)(b * Nn + n0 + nqT)) * Ct * Tt;
            #pragma unroll
            for (int q = 0; q < 4; ++q) {
                *(float4*)(obase + clo * Tt + tHv + q * 4) =
                    make_float4(olo[q*4], olo[q*4+1], olo[q*4+2], olo[q*4+3]);
                *(float4*)(obase + chi * Tt + tHv + q * 4) =
                    make_float4(ohi[q*4], ohi[q*4+1], ohi[q*4+2], ohi[q*4+3]);
            }
        }
        __syncthreads();
    }
}

// ---------------------------------------------------------------------------
extern "C" void kernel_launch(void* const* d_in, const int* in_sizes, int n_in,
                              void* d_out, int out_size)
{
    const float* x      = (const float*)d_in[0];
    const float* cheb   = (const float*)d_in[1];
    const float* theta  = (const float*)d_in[2];
    const float* w_time = (const float*)d_in[3];
    const float* b_time = (const float*)d_in[4];
    const float* w_res  = (const float*)d_in[5];
    const float* b_res  = (const float*)d_in[6];
    const float* gamma  = (const float*)d_in[7];
    const float* beta   = (const float*)d_in[8];
    float* out = (float*)d_out;

    cudaFuncSetAttribute(gemm_mma_kernel,
                         cudaFuncAttributeMaxDynamicSharedMemorySize, GEMM_SMEM);
    cudaFuncSetAttribute(fused_epi_tc,
                         cudaFuncAttributeMaxDynamicSharedMemorySize, ESMEM);

    prep_wt<<<54, 256>>>(w_time);
    convert_cheb<<<dim3(32, 32, 3), dim3(32, 8)>>>(cheb);
    convert_x<<<dim3(32, 3, 32), dim3(32, 8)>>>(x);
    gemm_mma_kernel<<<dim3(8, 3, 32), 256, GEMM_SMEM>>>();
    fused_epi_tc<<<dim3(Nn / GRP, Bb), 256, ESMEM>>>(
        x, theta, w_res, b_time, b_res, gamma, beta, out);
}